// round 1
// baseline (speedup 1.0000x reference)
#include <cuda_runtime.h>
#include <math.h>

// Problem constants (fixed by the dataset)
constexpr int kB    = 256;    // batch
constexpr int kN    = 1152;   // n_in
constexpr int kD    = 8;      // d_in
constexpr int kO    = 10;     // n_out
constexpr int kE    = 16;     // d_out
constexpr int kOE   = kO * kE;        // 160
constexpr int kWrow = kO * kD * kE;   // 1280 floats of W per n

// Tiling
constexpr int kNC = 8;    // n per block
constexpr int kBC = 8;    // batch per block
constexpr int kTH = 320;  // threads per block (kNC groups of 40 = 10 o x 4 e-groups)

// SMEM layout (floats). W region padded per-o to 136 to spread banks.
constexpr int kWStrideO = 136;
constexpr int kWStrideN = kO * kWStrideO;          // 1360
constexpr int kOffU     = kNC * kWStrideN;         // 10880
constexpr int kOffV     = kOffU + kNC * kD * kBC;  // 10880+512 = 11392
constexpr int kOffA     = kOffV + kOE * kBC;       // +1280 = 12672
constexpr int kOffBias  = kOffA + kNC * kBC * kO;  // +640 = 13312
constexpr int kSmemFloats = kOffBias + kNC * kO;   // 13392
constexpr int kSmemBytes  = kSmemFloats * 4;       // 53568

typedef unsigned long long u64;

// Persistent scratch (tiny): s accumulator and running v-sum
__device__ float g_s[kB * kOE];
__device__ float g_vsum[kB * kOE];

// packed fp32x2 helpers (FFMA2 path — ptxas won't auto-fuse; PTX only)
#define FMA2(d, a, b_) asm("fma.rn.f32x2 %0, %1, %2, %0;" : "+l"(d) : "l"(a), "l"(b_))
#define MUL2(d, a, b_) asm("mul.rn.f32x2 %0, %1, %2;" : "=l"(d) : "l"(a), "l"(b_))
#define PACK2(d, lo, hi) \
  asm("mov.b64 %0, {%1, %2};" : "=l"(d) : "r"(__float_as_uint(lo)), "r"(__float_as_uint(hi)))
#define UNPK2(lo, hi, v)                                                        \
  do {                                                                          \
    unsigned _l, _h;                                                            \
    asm("mov.b64 {%0, %1}, %2;" : "=r"(_l), "=r"(_h) : "l"(v));                 \
    lo = __uint_as_float(_l); hi = __uint_as_float(_h);                         \
  } while (0)

// One fused routing pass.
// MODE 0: c = 0.1 (softmax of zero logits)  -> s1
// MODE 1: c = softmax_o( <u_ji, g_vsum> )   -> s2 / s3
template <int MODE>
__global__ void __launch_bounds__(kTH, 2) pass_kernel(
    const float* __restrict__ u_i,
    const float* __restrict__ W,
    const float* __restrict__ bias)
{
  extern __shared__ float sm[];
  float* w_s = sm;                 // [nl][o(pad 136)][d*16+e]  — overlaid by s_part later
  float* u_s = sm + kOffU;         // [nl][d][b]  (b contiguous -> pre-packed f32x2 pairs)
  float* v_s = sm + kOffV;         // [oe][b]
  float* a_s = sm + kOffA;         // [grp][b][o] agreement logits -> softmax coeffs
  float* b_s = sm + kOffBias;      // [nl][o]

  const int tid = threadIdx.x;
  const int b0  = blockIdx.x * kBC;
  const int n0  = blockIdx.y * kNC;

  // ---- stage inputs ----
  for (int i = tid; i < kNC * kWrow; i += kTH) {
    int nl = i / kWrow; int rem = i - nl * kWrow;
    int o = rem >> 7; int de = rem & 127;
    w_s[nl * kWStrideN + o * kWStrideO + de] = W[(n0 + nl) * kWrow + rem];
  }
  for (int i = tid; i < kBC * kNC * kD; i += kTH) {
    int b = i >> 6; int nl = (i >> 3) & 7; int d = i & 7;
    u_s[nl * 64 + d * 8 + b] = u_i[((b0 + b) * kN + n0 + nl) * kD + d];
  }
  if (tid < kNC * kO)
    b_s[tid] = bias[(n0 + tid / kO) * kO + (tid % kO)];
  if (MODE) {
    for (int i = tid; i < kOE * kBC; i += kTH) {
      int b = i / kOE; int oe = i - b * kOE;
      v_s[oe * 8 + b] = g_vsum[(b0 + b) * kOE + oe];
    }
    for (int i = tid; i < kNC * kBC * kO; i += kTH) a_s[i] = 0.f;
  }
  __syncthreads();

  // thread identity: group = local n, then (o, e-group of 4)
  const int grp = tid / 40;
  const int r40 = tid - grp * 40;
  const int o   = r40 >> 2;
  const int eg  = r40 & 3;

  const float* wp = w_s + grp * kWStrideN + o * kWStrideO + eg * 4;
  const float* up = u_s + grp * 64;

  // acc[k][j]: k = batch pair (b=2k,2k+1), j = e offset; f32x2 packed over batch
  u64 acc[4][4];
  {
    float bv = b_s[grp * kO + o];
    u64 bp; PACK2(bp, bv, bv);
#pragma unroll
    for (int k = 0; k < 4; k++)
#pragma unroll
      for (int j = 0; j < 4; j++) acc[k][j] = bp;
  }

  // u_ji recompute: 128 FFMA2 per thread (256 FMA)
#pragma unroll
  for (int d = 0; d < kD; d++) {
    float4 w4 = *(const float4*)(wp + d * 16);
    u64 wd0, wd1, wd2, wd3;
    PACK2(wd0, w4.x, w4.x); PACK2(wd1, w4.y, w4.y);
    PACK2(wd2, w4.z, w4.z); PACK2(wd3, w4.w, w4.w);
    ulonglong2 ua = *(const ulonglong2*)(up + d * 8);      // batches (0,1),(2,3)
    ulonglong2 ub = *(const ulonglong2*)(up + d * 8 + 4);  // batches (4,5),(6,7)
    FMA2(acc[0][0], ua.x, wd0); FMA2(acc[0][1], ua.x, wd1);
    FMA2(acc[0][2], ua.x, wd2); FMA2(acc[0][3], ua.x, wd3);
    FMA2(acc[1][0], ua.y, wd0); FMA2(acc[1][1], ua.y, wd1);
    FMA2(acc[1][2], ua.y, wd2); FMA2(acc[1][3], ua.y, wd3);
    FMA2(acc[2][0], ub.x, wd0); FMA2(acc[2][1], ub.x, wd1);
    FMA2(acc[2][2], ub.x, wd2); FMA2(acc[2][3], ub.x, wd3);
    FMA2(acc[3][0], ub.y, wd0); FMA2(acc[3][1], ub.y, wd1);
    FMA2(acc[3][2], ub.y, wd2); FMA2(acc[3][3], ub.y, wd3);
  }

  // agreement logits: a[b][o] += <u_ji[b,o,:], v[b,o,:]>
  if (MODE) {
    u64 ag0 = 0ull, ag1 = 0ull, ag2 = 0ull, ag3 = 0ull;
    const float* vp = v_s + (o * 16 + eg * 4) * 8;
#pragma unroll
    for (int j = 0; j < 4; j++) {
      ulonglong2 va = *(const ulonglong2*)(vp + j * 8);
      ulonglong2 vb = *(const ulonglong2*)(vp + j * 8 + 4);
      FMA2(ag0, acc[0][j], va.x);
      FMA2(ag1, acc[1][j], va.y);
      FMA2(ag2, acc[2][j], vb.x);
      FMA2(ag3, acc[3][j], vb.y);
    }
    float lo, hi;
    float* ar = a_s + grp * (kBC * kO);
    UNPK2(lo, hi, ag0); atomicAdd(ar + 0 * kO + o, lo); atomicAdd(ar + 1 * kO + o, hi);
    UNPK2(lo, hi, ag1); atomicAdd(ar + 2 * kO + o, lo); atomicAdd(ar + 3 * kO + o, hi);
    UNPK2(lo, hi, ag2); atomicAdd(ar + 4 * kO + o, lo); atomicAdd(ar + 5 * kO + o, hi);
    UNPK2(lo, hi, ag3); atomicAdd(ar + 6 * kO + o, lo); atomicAdd(ar + 7 * kO + o, hi);
  }
  __syncthreads();  // W reads done; a_s atomics done

  if (MODE) {
    if (tid < kNC * kBC) {          // one (grp,b) row of 10 logits per thread
      float* row = a_s + tid * kO;
      float m = row[0];
#pragma unroll
      for (int i = 1; i < kO; i++) m = fmaxf(m, row[i]);
      float e[kO]; float s = 0.f;
#pragma unroll
      for (int i = 0; i < kO; i++) { e[i] = expf(row[i] - m); s += e[i]; }
      float inv = 1.f / s;
#pragma unroll
      for (int i = 0; i < kO; i++) row[i] = e[i] * inv;
    }
    __syncthreads();
  }

  // weight by c and write partials into the (now free) W region
  u64* sp2 = (u64*)sm;  // [grp][k][oe] as f32x2 (packed over batch pair)
  const int oebase = o * 16 + eg * 4;
#pragma unroll
  for (int k = 0; k < 4; k++) {
    float c0, c1;
    if (MODE) {
      c0 = a_s[grp * (kBC * kO) + (2 * k) * kO + o];
      c1 = a_s[grp * (kBC * kO) + (2 * k + 1) * kO + o];
    } else {
      c0 = 0.1f; c1 = 0.1f;
    }
    u64 cp; PACK2(cp, c0, c1);
#pragma unroll
    for (int j = 0; j < 4; j++) {
      u64 sv; MUL2(sv, acc[k][j], cp);
      sp2[(grp * 4 + k) * kOE + oebase + j] = sv;
    }
  }
  __syncthreads();

  // reduce over the 8 n-groups, one global atomicAdd per output element
  const float2* spf = (const float2*)sm;
  for (int i = tid; i < 4 * kOE; i += kTH) {
    int k = i / kOE; int oe = i - k * kOE;
    float sx = 0.f, sy = 0.f;
#pragma unroll
    for (int g = 0; g < kNC; g++) {
      float2 t = spf[(g * 4 + k) * kOE + oe];
      sx += t.x; sy += t.y;
    }
    atomicAdd(&g_s[(b0 + 2 * k) * kOE + oe], sx);
    atomicAdd(&g_s[(b0 + 2 * k + 1) * kOE + oe], sy);
  }
}

__global__ void zero_s_kernel() {
  int i = blockIdx.x * blockDim.x + threadIdx.x;
  if (i < kB * kOE) g_s[i] = 0.f;
}

// v = squash(s); write to g_vsum (optionally accumulating) or to out
__global__ void squash_kernel(float* __restrict__ out, int to_out, int accumulate) {
  int r = blockIdx.x * blockDim.x + threadIdx.x;
  if (r >= kB * kO) return;
  const float* sp = g_s + r * kE;
  float v[kE]; float n2 = 0.f;
#pragma unroll
  for (int i = 0; i < kE; i++) { v[i] = sp[i]; n2 += v[i] * v[i]; }
  float norm = sqrtf(n2);
  float f = norm / (1.f + n2);
  if (to_out) {
    float* dst = out + r * kE;
#pragma unroll
    for (int i = 0; i < kE; i++) dst[i] = v[i] * f;
  } else {
    float* dst = g_vsum + r * kE;
    if (accumulate) {
#pragma unroll
      for (int i = 0; i < kE; i++) dst[i] += v[i] * f;
    } else {
#pragma unroll
      for (int i = 0; i < kE; i++) dst[i] = v[i] * f;
    }
  }
}

extern "C" void kernel_launch(void* const* d_in, const int* in_sizes, int n_in,
                              void* d_out, int out_size) {
  const float* u    = (const float*)d_in[0];
  const float* W    = (const float*)d_in[1];
  const float* bias = (const float*)d_in[2];
  float* out = (float*)d_out;

  // >48KB dynamic smem opt-in (idempotent; not a stream op)
  cudaFuncSetAttribute((const void*)pass_kernel<0>,
                       cudaFuncAttributeMaxDynamicSharedMemorySize, kSmemBytes);
  cudaFuncSetAttribute((const void*)pass_kernel<1>,
                       cudaFuncAttributeMaxDynamicSharedMemorySize, kSmemBytes);

  dim3 grid(kB / kBC, kN / kNC);  // (32, 144)

  // iter 1: uniform c -> s1 -> v1 (g_vsum = v1)
  zero_s_kernel<<<(kB * kOE + 255) / 256, 256>>>();
  pass_kernel<0><<<grid, kTH, kSmemBytes>>>(u, W, bias);
  squash_kernel<<<(kB * kO + 255) / 256, 256>>>(nullptr, 0, 0);

  // iter 2: logits = <u_ji, v1> -> s2 -> v2 (g_vsum = v1 + v2)
  zero_s_kernel<<<(kB * kOE + 255) / 256, 256>>>();
  pass_kernel<1><<<grid, kTH, kSmemBytes>>>(u, W, bias);
  squash_kernel<<<(kB * kO + 255) / 256, 256>>>(nullptr, 0, 1);

  // iter 3: logits = <u_ji, v1+v2> -> s3 -> v3 = output
  zero_s_kernel<<<(kB * kOE + 255) / 256, 256>>>();
  pass_kernel<1><<<grid, kTH, kSmemBytes>>>(u, W, bias);
  squash_kernel<<<(kB * kO + 255) / 256, 256>>>(out, 1, 0);
}

// round 2
// speedup vs baseline: 1.2972x; 1.2972x over previous
#include <cuda_runtime.h>
#include <math.h>

// Problem constants
constexpr int kB = 256, kN = 1152, kD = 8, kO = 10, kE = 16;
constexpr int kOE = kO * kE;          // 160
constexpr int kWrow = kO * kD * kE;   // 1280

// Tiling
constexpr int kBC = 16;               // batch per block
constexpr int kNC = 4;                // n per chunk
constexpr int kNCH = 8;               // chunks per block
constexpr int kNPB = kNC * kNCH;      // 32 n per block
constexpr int kGX = kB / kBC;         // 16
constexpr int kGY = kN / kNPB;        // 36
constexpr int kTH = 320;              // (bg2)x(grp4)x(o10)x(eg4)

// SMEM layout (floats)
constexpr int kWSO = 132;                       // per-o stride (conflict-free)
constexpr int kWSN = kO * kWSO;                 // 1320
constexpr int kOffU = kNC * kWSN;               // 5280
constexpr int kOffV = kOffU + kNC * kD * kBC;   // 5792
constexpr int kOffA = kOffV + kOE * kBC;        // 8352
constexpr int kOffB = kOffA + kNC * kBC * kO;   // 8992
constexpr int kSmemFloats = 10240;              // >= 9032; overlay: 5120 u64 s-dump

typedef unsigned long long u64;

// Partials: [n-block][batch][oe]  (5.9 MB, L2-resident)
__device__ float g_part[(size_t)kGY * kB * kOE];
__device__ float g_vsum[kB * kOE];

#define FMA2(d, a, b_) asm("fma.rn.f32x2 %0, %1, %2, %0;" : "+l"(d) : "l"(a), "l"(b_))
#define PACK2(d, lo, hi) \
  asm("mov.b64 %0, {%1, %2};" : "=l"(d) : "r"(__float_as_uint(lo)), "r"(__float_as_uint(hi)))
#define UNPK2(lo, hi, v)                                                \
  do {                                                                  \
    unsigned _l, _h;                                                    \
    asm("mov.b64 {%0, %1}, %2;" : "=r"(_l), "=r"(_h) : "l"(v));         \
    lo = __uint_as_float(_l); hi = __uint_as_float(_h);                 \
  } while (0)

__global__ void noop_kernel() {}

// One routing pass. MODE 0: c = 0.1 (softmax of zeros). MODE 1: c = softmax_o(<u_ji, g_vsum>).
template <int MODE>
__global__ void __launch_bounds__(kTH, 2) pass_kernel(
    const float* __restrict__ u_i,
    const float* __restrict__ W,
    const float* __restrict__ bias)
{
  __shared__ __align__(16) float sm[kSmemFloats];
  float* w_s = sm;                // [nl][o(pad132)][d*16+e]
  float* u_s = sm + kOffU;        // [nl][d][b16]
  float* v_s = sm + kOffV;        // [oe][b16]
  float* a_s = sm + kOffA;        // [nl][b16][o]
  float* b_s = sm + kOffB;        // [nl][o]

  const int tid = threadIdx.x;
  const int b0  = blockIdx.x * kBC;
  const int nb0 = blockIdx.y * kNPB;

  const int eg  = tid & 3;
  const int q   = tid >> 2;
  const int o   = q % 10;
  const int g2  = q / 10;
  const int grp = g2 & 3;
  const int bg  = g2 >> 2;

  // stage v (once per pass)
  if (MODE) {
    for (int i = tid; i < kOE * kBC; i += kTH) {
      int b = i / kOE, oe = i - b * kOE;
      v_s[oe * 16 + b] = g_vsum[(b0 + b) * kOE + oe];
    }
  }

  u64 s[4][4];
#pragma unroll
  for (int k = 0; k < 4; k++)
#pragma unroll
    for (int j = 0; j < 4; j++) s[k][j] = 0ull;

  for (int ch = 0; ch < kNCH; ch++) {
    const int n0 = nb0 + ch * kNC;
    __syncthreads();  // protect prev chunk's smem reads

    // stage W chunk: 4n x 1280 floats, coalesced float4
    {
      const float4* Wg = (const float4*)(W + (size_t)n0 * kWrow);
      for (int i = tid; i < kNC * 320; i += kTH) {
        int nl = i / 320, r = i - nl * 320;
        int oo = r >> 5, de4 = r & 31;
        float4 w4 = Wg[(size_t)nl * 320 + r];
        *(float4*)&w_s[nl * kWSN + oo * kWSO + de4 * 4] = w4;
      }
    }
    // stage u chunk: 4n x 16b x 8d -> [nl][d][b]
    if (tid < 64) {
      int b = tid & 15, nl = tid >> 4;
      const float4* up4 = (const float4*)(u_i + ((size_t)(b0 + b) * kN + n0 + nl) * kD);
      float4 a4 = up4[0], c4 = up4[1];
      float* du = &u_s[nl * 128 + b];
      du[0] = a4.x; du[16] = a4.y; du[32] = a4.z; du[48] = a4.w;
      du[64] = c4.x; du[80] = c4.y; du[96] = c4.z; du[112] = c4.w;
    }
    if (tid < kNC * kO)
      b_s[tid] = bias[(n0 + tid / 10) * 10 + tid % 10];
    __syncthreads();

    // recompute u_ji tile (incl. bias) into acc
    u64 acc[4][4];
    {
      float bv = b_s[grp * 10 + o];
      u64 bp; PACK2(bp, bv, bv);
#pragma unroll
      for (int k = 0; k < 4; k++)
#pragma unroll
        for (int j = 0; j < 4; j++) acc[k][j] = bp;
    }
    const float* wp = w_s + grp * kWSN + o * kWSO + eg * 4;
    const float* up = u_s + grp * 128 + bg * 8;
#pragma unroll
    for (int d = 0; d < kD; d++) {
      float4 w4 = *(const float4*)(wp + d * 16);
      u64 w0, w1, w2, w3;
      PACK2(w0, w4.x, w4.x); PACK2(w1, w4.y, w4.y);
      PACK2(w2, w4.z, w4.z); PACK2(w3, w4.w, w4.w);
      ulonglong2 ua = *(const ulonglong2*)(up + d * 16);
      ulonglong2 ub = *(const ulonglong2*)(up + d * 16 + 4);
      FMA2(acc[0][0], ua.x, w0); FMA2(acc[0][1], ua.x, w1);
      FMA2(acc[0][2], ua.x, w2); FMA2(acc[0][3], ua.x, w3);
      FMA2(acc[1][0], ua.y, w0); FMA2(acc[1][1], ua.y, w1);
      FMA2(acc[1][2], ua.y, w2); FMA2(acc[1][3], ua.y, w3);
      FMA2(acc[2][0], ub.x, w0); FMA2(acc[2][1], ub.x, w1);
      FMA2(acc[2][2], ub.x, w2); FMA2(acc[2][3], ub.x, w3);
      FMA2(acc[3][0], ub.y, w0); FMA2(acc[3][1], ub.y, w1);
      FMA2(acc[3][2], ub.y, w2); FMA2(acc[3][3], ub.y, w3);
    }

    float cl[4], chv[4];
    if (MODE) {
      // agreement logits: <u_ji, v> summed over e (j in regs, eg via shfl)
      u64 ag[4] = {0ull, 0ull, 0ull, 0ull};
      const float* vp = v_s + (o * 16 + eg * 4) * 16 + bg * 8;
#pragma unroll
      for (int j = 0; j < 4; j++) {
        ulonglong2 va = *(const ulonglong2*)(vp + j * 16);
        ulonglong2 vb = *(const ulonglong2*)(vp + j * 16 + 4);
        FMA2(ag[0], acc[0][j], va.x);
        FMA2(ag[1], acc[1][j], va.y);
        FMA2(ag[2], acc[2][j], vb.x);
        FMA2(ag[3], acc[3][j], vb.y);
      }
      float al[4], ah[4];
#pragma unroll
      for (int k = 0; k < 4; k++) {
        UNPK2(al[k], ah[k], ag[k]);
        al[k] += __shfl_xor_sync(0xffffffffu, al[k], 1);
        al[k] += __shfl_xor_sync(0xffffffffu, al[k], 2);
        ah[k] += __shfl_xor_sync(0xffffffffu, ah[k], 1);
        ah[k] += __shfl_xor_sync(0xffffffffu, ah[k], 2);
      }
      if (eg == 0) {
        float* ar = a_s + grp * 160 + bg * 80 + o;
        ar[0]  = al[0]; ar[10] = ah[0];
        ar[20] = al[1]; ar[30] = ah[1];
        ar[40] = al[2]; ar[50] = ah[2];
        ar[60] = al[3]; ar[70] = ah[3];
      }
      __syncthreads();
      if (tid < kNC * kBC) {  // softmax over o per (nl, b)
        float* row = a_s + tid * 10;
        float m = row[0];
#pragma unroll
        for (int i = 1; i < kO; i++) m = fmaxf(m, row[i]);
        float e[kO]; float ss = 0.f;
#pragma unroll
        for (int i = 0; i < kO; i++) { e[i] = __expf(row[i] - m); ss += e[i]; }
        float inv = 1.f / ss;
#pragma unroll
        for (int i = 0; i < kO; i++) row[i] = e[i] * inv;
      }
      __syncthreads();
      const float* ar = a_s + grp * 160 + bg * 80 + o;
#pragma unroll
      for (int k = 0; k < 4; k++) { cl[k] = ar[k * 20]; chv[k] = ar[k * 20 + 10]; }
    }

    // s += c * u_ji
#pragma unroll
    for (int k = 0; k < 4; k++) {
      u64 cp;
      if (MODE) { PACK2(cp, cl[k], chv[k]); }
      else      { PACK2(cp, 0.1f, 0.1f); }
#pragma unroll
      for (int j = 0; j < 4; j++) FMA2(s[k][j], acc[k][j], cp);
    }
  }

  // block-level reduce over grp, then plain global write of partials
  __syncthreads();
  u64* sd = (u64*)sm;
  const int row = (bg * 10 + o) * 4 + eg;  // 0..79
#pragma unroll
  for (int k = 0; k < 4; k++)
#pragma unroll
    for (int j = 0; j < 4; j++) sd[(row * 4 + grp) * 16 + k * 4 + j] = s[k][j];
  __syncthreads();
  {
    const int row2 = tid >> 2, k = tid & 3;
    const int eg2 = row2 & 3, o2 = (row2 >> 2) % 10, bg2 = row2 / 40;
    float sx[4], sy[4];
#pragma unroll
    for (int j = 0; j < 4; j++) { sx[j] = 0.f; sy[j] = 0.f; }
#pragma unroll
    for (int g = 0; g < 4; g++)
#pragma unroll
      for (int j = 0; j < 4; j++) {
        float lo, hi; UNPK2(lo, hi, sd[(row2 * 4 + g) * 16 + k * 4 + j]);
        sx[j] += lo; sy[j] += hi;
      }
    const int bA = b0 + bg2 * 8 + 2 * k;
    float* dp = &g_part[((size_t)blockIdx.y * kB + bA) * kOE + o2 * 16 + eg2 * 4];
    *(float4*)dp         = make_float4(sx[0], sx[1], sx[2], sx[3]);
    *(float4*)(dp + kOE) = make_float4(sy[0], sy[1], sy[2], sy[3]);
  }
}

// reduce 36 partials, squash; mode 0: vsum = v; 1: vsum += v; 2: out = v
__global__ void squash_kernel(float* __restrict__ out, int mode) {
  int r = blockIdx.x * blockDim.x + threadIdx.x;
  if (r >= kB * kO) return;
  int b = r / 10, oo = r % 10;
  const float* pp = g_part + (size_t)b * kOE + oo * 16;
  float4 v0 = {0,0,0,0}, v1 = {0,0,0,0}, v2 = {0,0,0,0}, v3 = {0,0,0,0};
  for (int p = 0; p < kGY; p++) {
    const float4* q4 = (const float4*)(pp + (size_t)p * kB * kOE);
    float4 a = q4[0], bq = q4[1], c = q4[2], d = q4[3];
    v0.x += a.x; v0.y += a.y; v0.z += a.z; v0.w += a.w;
    v1.x += bq.x; v1.y += bq.y; v1.z += bq.z; v1.w += bq.w;
    v2.x += c.x; v2.y += c.y; v2.z += c.z; v2.w += c.w;
    v3.x += d.x; v3.y += d.y; v3.z += d.z; v3.w += d.w;
  }
  float n2 = v0.x*v0.x + v0.y*v0.y + v0.z*v0.z + v0.w*v0.w
           + v1.x*v1.x + v1.y*v1.y + v1.z*v1.z + v1.w*v1.w
           + v2.x*v2.x + v2.y*v2.y + v2.z*v2.z + v2.w*v2.w
           + v3.x*v3.x + v3.y*v3.y + v3.z*v3.z + v3.w*v3.w;
  float f = sqrtf(n2) / (1.f + n2);
  float vv[16] = {v0.x,v0.y,v0.z,v0.w, v1.x,v1.y,v1.z,v1.w,
                  v2.x,v2.y,v2.z,v2.w, v3.x,v3.y,v3.z,v3.w};
  if (mode == 2) {
    float* dst = out + (size_t)r * kE;
#pragma unroll
    for (int i = 0; i < kE; i++) dst[i] = vv[i] * f;
  } else if (mode == 1) {
    float* dst = g_vsum + (size_t)r * kE;
#pragma unroll
    for (int i = 0; i < kE; i++) dst[i] += vv[i] * f;
  } else {
    float* dst = g_vsum + (size_t)r * kE;
#pragma unroll
    for (int i = 0; i < kE; i++) dst[i] = vv[i] * f;
  }
}

extern "C" void kernel_launch(void* const* d_in, const int* in_sizes, int n_in,
                              void* d_out, int out_size) {
  const float* u    = (const float*)d_in[0];
  const float* W    = (const float*)d_in[1];
  const float* bias = (const float*)d_in[2];
  float* out = (float*)d_out;

  dim3 grid(kGX, kGY);

  noop_kernel<<<1, 32>>>();  // shifts ncu -s 5 onto pass_kernel<1>

  // iter 1: c uniform -> s1 partials -> v1
  pass_kernel<0><<<grid, kTH>>>(u, W, bias);
  squash_kernel<<<10, 256>>>(nullptr, 0);

  // iter 2: logits = <u_ji, v1> -> s2 -> vsum = v1+v2
  pass_kernel<1><<<grid, kTH>>>(u, W, bias);
  squash_kernel<<<10, 256>>>(nullptr, 1);

  // iter 3: logits = <u_ji, v1+v2> -> s3 -> out
  pass_kernel<1><<<grid, kTH>>>(u, W, bias);
  squash_kernel<<<10, 256>>>(out, 2);
}

// round 3
// speedup vs baseline: 1.3438x; 1.0359x over previous
#include <cuda_runtime.h>
#include <math.h>

// Problem constants
constexpr int kB = 256, kN = 1152, kD = 8, kO = 10, kE = 16;
constexpr int kOE = kO * kE;  // 160

// Tiling: block owns 8 n, loops all 256 batches in 32 chunks of 8.
constexpr int kNL   = 8;
constexpr int kTH   = 320;          // tid = nl + 8*eg + 32*o  (warp == o)
constexpr int kGrid = kN / kNL;     // 144
constexpr int kCB   = 8;            // batches per chunk
constexpr int kNCH  = kB / kCB;     // 32

// SMEM (floats)
constexpr int kUSnl = 2052;                 // u_s nl stride (banks: nl*4)
constexpr int kUSd  = 256;                  // u_s d stride
constexpr int kOffA = kNL * kUSnl;          // 16416 : a_s [nl][84]
constexpr int kAPad = 84;
constexpr int kOffSD = kOffA + kNL * kAPad; // 17088 : sd 5120 u64
constexpr int kSmemFloats = kOffSD + 10240; // 27328
constexpr int kSmemBytes  = kSmemFloats * 4;

typedef unsigned long long u64;

__device__ float g_part[(size_t)kGrid * kB * kOE];  // 23.6 MB
__device__ float g_vsum[kB * kOE];

#define FMA2(d, a, b_) asm("fma.rn.f32x2 %0, %1, %2, %0;" : "+l"(d) : "l"(a), "l"(b_))
#define MUL2(d, a, b_) asm("mul.rn.f32x2 %0, %1, %2;" : "=l"(d) : "l"(a), "l"(b_))
#define PACK2(d, lo, hi) \
  asm("mov.b64 %0, {%1, %2};" : "=l"(d) : "r"(__float_as_uint(lo)), "r"(__float_as_uint(hi)))
#define UNPK2(lo, hi, v)                                                \
  do {                                                                  \
    unsigned _l, _h;                                                    \
    asm("mov.b64 {%0, %1}, %2;" : "=r"(_l), "=r"(_h) : "l"(v));         \
    lo = __uint_as_float(_l); hi = __uint_as_float(_h);                 \
  } while (0)

__global__ void noop_kernel() {}

// MODE 0: c = 0.1.  MODE 1: c = softmax_o(<u_ji, g_vsum>).
template <int MODE>
__global__ void __launch_bounds__(kTH, 1) pass_kernel(
    const float* __restrict__ u_i,
    const float* __restrict__ W,
    const float* __restrict__ bias)
{
  extern __shared__ float sm[];
  float* u_s = sm;                  // [nl(2052)][d(256)][b]
  float* a_s = sm + kOffA;          // [nl][84] logits
  u64*   sd  = (u64*)(sm + kOffSD); // [slot 640][nl 8]

  const int tid = threadIdx.x;
  const int nl  = tid & 7;
  const int eg  = (tid >> 3) & 3;
  const int o   = tid >> 5;         // warp id
  const int n0  = blockIdx.x * kNL;

  // ---- W slice into registers (once per pass) ----
  float w[kD][4];
  {
    const float* Wp = W + ((size_t)(n0 + nl) * kO + o) * (kD * kE) + eg * 4;
#pragma unroll
    for (int d = 0; d < kD; d++) {
      float4 w4 = *(const float4*)(Wp + d * kE);
      w[d][0] = w4.x; w[d][1] = w4.y; w[d][2] = w4.z; w[d][3] = w4.w;
    }
  }
  const float bv = bias[(n0 + nl) * kO + o];
  u64 bp; PACK2(bp, bv, bv);

  // ---- stage u once: [b][n][d] -> [nl][d][b] ----
  for (int i = tid; i < kB * kNL * 2; i += kTH) {
    int b = i >> 4, nl2 = (i >> 1) & 7, h = i & 1;
    float4 t = *(const float4*)(u_i + ((size_t)b * kN + n0 + nl2) * kD + h * 4);
    float* du = u_s + nl2 * kUSnl + h * 4 * kUSd + b;
    du[0] = t.x; du[kUSd] = t.y; du[2 * kUSd] = t.z; du[3 * kUSd] = t.w;
  }
  __syncthreads();

  const float* up_base = u_s + nl * kUSnl;

  for (int ch = 0; ch < kNCH; ch++) {
    const int bc = ch * kCB;

    // prefetch v (gmem, L1-hot) before the FMA block
    float vr[kCB][4];
    if (MODE) {
#pragma unroll
      for (int k2 = 0; k2 < kCB; k2++) {
        float4 t = *(const float4*)(g_vsum + (size_t)(bc + k2) * kOE + o * kE + eg * 4);
        vr[k2][0] = t.x; vr[k2][1] = t.y; vr[k2][2] = t.z; vr[k2][3] = t.w;
      }
    }

    // ---- u_ji tile (bias included); f32x2 packed over batch pairs ----
    u64 acc[4][4];
#pragma unroll
    for (int k = 0; k < 4; k++)
#pragma unroll
      for (int j = 0; j < 4; j++) acc[k][j] = bp;

    const float* up = up_base + bc;
#pragma unroll
    for (int d = 0; d < kD; d++) {
      ulonglong2 ua = *(const ulonglong2*)(up + d * kUSd);      // b pairs (0,1),(2,3)
      ulonglong2 ub = *(const ulonglong2*)(up + d * kUSd + 4);  // b pairs (4,5),(6,7)
      u64 w2[4];
      PACK2(w2[0], w[d][0], w[d][0]); PACK2(w2[1], w[d][1], w[d][1]);
      PACK2(w2[2], w[d][2], w[d][2]); PACK2(w2[3], w[d][3], w[d][3]);
      FMA2(acc[0][0], ua.x, w2[0]); FMA2(acc[0][1], ua.x, w2[1]);
      FMA2(acc[0][2], ua.x, w2[2]); FMA2(acc[0][3], ua.x, w2[3]);
      FMA2(acc[1][0], ua.y, w2[0]); FMA2(acc[1][1], ua.y, w2[1]);
      FMA2(acc[1][2], ua.y, w2[2]); FMA2(acc[1][3], ua.y, w2[3]);
      FMA2(acc[2][0], ub.x, w2[0]); FMA2(acc[2][1], ub.x, w2[1]);
      FMA2(acc[2][2], ub.x, w2[2]); FMA2(acc[2][3], ub.x, w2[3]);
      FMA2(acc[3][0], ub.y, w2[0]); FMA2(acc[3][1], ub.y, w2[1]);
      FMA2(acc[3][2], ub.y, w2[2]); FMA2(acc[3][3], ub.y, w2[3]);
    }

    float cl[4], chv[4];
    if (MODE) {
      // agreement logits, reduced over e: j in regs, eg via shfl(8,16)
      u64 ag[4] = {0ull, 0ull, 0ull, 0ull};
#pragma unroll
      for (int k = 0; k < 4; k++)
#pragma unroll
        for (int j = 0; j < 4; j++) {
          u64 vp; PACK2(vp, vr[2 * k][j], vr[2 * k + 1][j]);
          FMA2(ag[k], acc[k][j], vp);
        }
      float al[4], ah[4];
#pragma unroll
      for (int k = 0; k < 4; k++) {
        UNPK2(al[k], ah[k], ag[k]);
        al[k] += __shfl_xor_sync(0xffffffffu, al[k], 8);
        al[k] += __shfl_xor_sync(0xffffffffu, al[k], 16);
        ah[k] += __shfl_xor_sync(0xffffffffu, ah[k], 8);
        ah[k] += __shfl_xor_sync(0xffffffffu, ah[k], 16);
      }
      if (eg == 0) {
        float* ar = a_s + nl * kAPad + o;
#pragma unroll
        for (int k = 0; k < 4; k++) {
          ar[(2 * k) * kO]     = al[k];
          ar[(2 * k + 1) * kO] = ah[k];
        }
      }
      __syncthreads();
      if (tid < 64) {  // softmax over o for each (nl, b-of-chunk)
        float* row = a_s + (tid & 7) * kAPad + (tid >> 3) * kO;
        float m = row[0];
#pragma unroll
        for (int i = 1; i < kO; i++) m = fmaxf(m, row[i]);
        float e[kO]; float ss = 0.f;
#pragma unroll
        for (int i = 0; i < kO; i++) { e[i] = __expf(row[i] - m); ss += e[i]; }
        float inv = 1.f / ss;
#pragma unroll
        for (int i = 0; i < kO; i++) row[i] = e[i] * inv;
      }
      __syncthreads();
      const float* ar = a_s + nl * kAPad + o;
#pragma unroll
      for (int k = 0; k < 4; k++) {
        cl[k]  = ar[(2 * k) * kO];
        chv[k] = ar[(2 * k + 1) * kO];
      }
    }

    // ---- s = c * u_ji, dump to sd for cross-nl reduction ----
#pragma unroll
    for (int k = 0; k < 4; k++) {
      u64 cp;
      if (MODE) { PACK2(cp, cl[k], chv[k]); }
      else      { PACK2(cp, 0.1f, 0.1f); }
#pragma unroll
      for (int j = 0; j < 4; j++) {
        u64 sv; MUL2(sv, acc[k][j], cp);
        sd[(size_t)((((o * 4 + k) * 4 + j) * 4 + eg)) * 8 + nl] = sv;
      }
    }
    __syncthreads();

    // reduce over nl (8) and store partials: 640 u64 outputs, 2 per thread
    {
#pragma unroll
      for (int t2 = 0; t2 < 2; t2++) {
        int slot = tid * 2 + t2;
        const u64* sp = sd + (size_t)slot * 8;
        float sx = 0.f, sy = 0.f;
#pragma unroll
        for (int g = 0; g < 8; g++) {
          float lo, hi; UNPK2(lo, hi, sp[g]);
          sx += lo; sy += hi;
        }
        int egs = slot & 3, js = (slot >> 2) & 3, ks = (slot >> 4) & 3, os = slot >> 6;
        int oe = os * kE + egs * 4 + js;
        float* dp = &g_part[((size_t)blockIdx.x * kB + bc + 2 * ks) * kOE + oe];
        dp[0]   = sx;
        dp[kOE] = sy;
      }
    }
    __syncthreads();
  }
}

// Reduce 144 partials + squash. 10240 threads: (b,o) x e-quarter; n2 via shfl.
__global__ void squash_kernel(float* __restrict__ out, int mode) {
  int gt = blockIdx.x * blockDim.x + threadIdx.x;
  if (gt >= kB * kO * 4) return;
  int eq = gt & 3, row = gt >> 2;      // row = b*10 + o
  const float* pp = g_part + (size_t)row * kE + eq * 4;
  float4 a = {0.f, 0.f, 0.f, 0.f};
#pragma unroll 4
  for (int p = 0; p < kGrid; p++) {
    float4 t = *(const float4*)(pp + (size_t)p * kB * kOE);
    a.x += t.x; a.y += t.y; a.z += t.z; a.w += t.w;
  }
  float n2 = a.x * a.x + a.y * a.y + a.z * a.z + a.w * a.w;
  n2 += __shfl_xor_sync(0xffffffffu, n2, 1);
  n2 += __shfl_xor_sync(0xffffffffu, n2, 2);
  float f = sqrtf(n2) / (1.f + n2);
  float4 v = make_float4(a.x * f, a.y * f, a.z * f, a.w * f);
  if (mode == 2) {
    *(float4*)(out + (size_t)row * kE + eq * 4) = v;
  } else if (mode == 1) {
    float4 old = *(const float4*)(g_vsum + (size_t)row * kE + eq * 4);
    v.x += old.x; v.y += old.y; v.z += old.z; v.w += old.w;
    *(float4*)(g_vsum + (size_t)row * kE + eq * 4) = v;
  } else {
    *(float4*)(g_vsum + (size_t)row * kE + eq * 4) = v;
  }
}

extern "C" void kernel_launch(void* const* d_in, const int* in_sizes, int n_in,
                              void* d_out, int out_size) {
  const float* u    = (const float*)d_in[0];
  const float* W    = (const float*)d_in[1];
  const float* bias = (const float*)d_in[2];
  float* out = (float*)d_out;

  cudaFuncSetAttribute((const void*)pass_kernel<0>,
                       cudaFuncAttributeMaxDynamicSharedMemorySize, kSmemBytes);
  cudaFuncSetAttribute((const void*)pass_kernel<1>,
                       cudaFuncAttributeMaxDynamicSharedMemorySize, kSmemBytes);

  noop_kernel<<<1, 32>>>();  // keeps ncu -s 5 -c 1 on pass_kernel<1>

  pass_kernel<0><<<kGrid, kTH, kSmemBytes>>>(u, W, bias);
  squash_kernel<<<40, 256>>>(nullptr, 0);

  pass_kernel<1><<<kGrid, kTH, kSmemBytes>>>(u, W, bias);
  squash_kernel<<<40, 256>>>(nullptr, 1);

  pass_kernel<1><<<kGrid, kTH, kSmemBytes>>>(u, W, bias);
  squash_kernel<<<40, 256>>>(out, 2);
}

// round 4
// speedup vs baseline: 2.4046x; 1.7893x over previous
#include <cuda_runtime.h>
#include <math.h>

// Problem constants
constexpr int kB = 256, kN = 1152, kD = 8, kO = 10, kE = 16;
constexpr int kOE = kO * kE;  // 160

// Tiling: block owns 8 n, loops all 256 batches in 32 chunks of 8.
constexpr int kNL   = 8;
constexpr int kTH   = 320;          // tid = nl + 8*eg + 32*o  (warp == o)
constexpr int kGrid = kN / kNL;     // 144
constexpr int kCB   = 8;            // batches per chunk
constexpr int kNCH  = kB / kCB;     // 32

// SMEM (floats)
constexpr int kUSnl = 2052;                 // u_s nl stride (banks: nl*4, conflict-free)
constexpr int kUSd  = 256;                  // u_s d stride
constexpr int kOffA = kNL * kUSnl;          // 16416
constexpr int kAPad = 84;
constexpr int kABuf = kNL * kAPad;          // 672 (double-buffered logits)
constexpr int kSmemFloats = kOffA + 2 * kABuf;  // 17760
constexpr int kSmemBytes  = kSmemFloats * 4;    // 71040

typedef unsigned long long u64;

__device__ float g_part[(size_t)kGrid * kB * kOE];  // 23.6 MB
__device__ float g_vsum[kB * kOE];

#define FMA2(d, a, b_) asm("fma.rn.f32x2 %0, %1, %2, %0;" : "+l"(d) : "l"(a), "l"(b_))
#define MUL2(d, a, b_) asm("mul.rn.f32x2 %0, %1, %2;" : "=l"(d) : "l"(a), "l"(b_))
#define ADD2(d, a, b_) asm("add.rn.f32x2 %0, %1, %2;" : "=l"(d) : "l"(a), "l"(b_))
#define PACK2(d, lo, hi) \
  asm("mov.b64 %0, {%1, %2};" : "=l"(d) : "r"(__float_as_uint(lo)), "r"(__float_as_uint(hi)))
#define UNPK2(lo, hi, v)                                                \
  do {                                                                  \
    unsigned _l, _h;                                                    \
    asm("mov.b64 {%0, %1}, %2;" : "=r"(_l), "=r"(_h) : "l"(v));         \
    lo = __uint_as_float(_l); hi = __uint_as_float(_h);                 \
  } while (0)

__global__ void noop_kernel() {}

// MODE 0: c = 0.1.  MODE 1: c = softmax_o(<u_ji, g_vsum>).
template <int MODE>
__global__ void __launch_bounds__(kTH, 1) pass_kernel(
    const float* __restrict__ u_i,
    const float* __restrict__ W,
    const float* __restrict__ bias)
{
  extern __shared__ float sm[];
  float* u_s = sm;                  // [nl(2052)][d(256)][b]
  float* a_s = sm + kOffA;          // 2 x [nl][84] logits (double-buffered)

  const int tid = threadIdx.x;
  const int nl  = tid & 7;
  const int eg  = (tid >> 3) & 3;
  const int o   = tid >> 5;         // warp id
  const int n0  = blockIdx.x * kNL;

  // ---- W slice into registers (once per pass) ----
  float w[kD][4];
  {
    const float* Wp = W + ((size_t)(n0 + nl) * kO + o) * (kD * kE) + eg * 4;
#pragma unroll
    for (int d = 0; d < kD; d++) {
      float4 w4 = *(const float4*)(Wp + d * kE);
      w[d][0] = w4.x; w[d][1] = w4.y; w[d][2] = w4.z; w[d][3] = w4.w;
    }
  }
  const float bv = bias[(n0 + nl) * kO + o];
  u64 bp; PACK2(bp, bv, bv);

  // ---- stage u once: [b][n][d] -> [nl][d][b] ----
  for (int i = tid; i < kB * kNL * 2; i += kTH) {
    int b = i >> 4, nl2 = (i >> 1) & 7, h = i & 1;
    float4 t = *(const float4*)(u_i + ((size_t)b * kN + n0 + nl2) * kD + h * 4);
    float* du = u_s + nl2 * kUSnl + h * 4 * kUSd + b;
    du[0] = t.x; du[kUSd] = t.y; du[2 * kUSd] = t.z; du[3 * kUSd] = t.w;
  }
  __syncthreads();

  const float* up_base = u_s + nl * kUSnl;
  const int mm = ((nl >> 2) & 1) * 8 + ((nl >> 1) & 1) * 4 + (nl & 1) * 2;
  const int kk = mm >> 2, j0 = mm & 3;  // this lane's final (batch-pair, e-pair)

  for (int ch = 0; ch < kNCH; ch++) {
    const int bc = ch * kCB;
    float* ab = a_s + (ch & 1) * kABuf;

    // prefetch v (gmem, L1-hot)
    float vr[kCB][4];
    if (MODE) {
#pragma unroll
      for (int k2 = 0; k2 < kCB; k2++) {
        float4 t = *(const float4*)(g_vsum + (size_t)(bc + k2) * kOE + o * kE + eg * 4);
        vr[k2][0] = t.x; vr[k2][1] = t.y; vr[k2][2] = t.z; vr[k2][3] = t.w;
      }
    }

    // ---- u_ji tile (bias included); f32x2 packed over batch pairs ----
    u64 acc[4][4];
#pragma unroll
    for (int k = 0; k < 4; k++)
#pragma unroll
      for (int j = 0; j < 4; j++) acc[k][j] = bp;

    const float* up = up_base + bc;
#pragma unroll
    for (int d = 0; d < kD; d++) {
      ulonglong2 ua = *(const ulonglong2*)(up + d * kUSd);      // b (0,1),(2,3)
      ulonglong2 ub = *(const ulonglong2*)(up + d * kUSd + 4);  // b (4,5),(6,7)
      u64 w2[4];
      PACK2(w2[0], w[d][0], w[d][0]); PACK2(w2[1], w[d][1], w[d][1]);
      PACK2(w2[2], w[d][2], w[d][2]); PACK2(w2[3], w[d][3], w[d][3]);
      FMA2(acc[0][0], ua.x, w2[0]); FMA2(acc[0][1], ua.x, w2[1]);
      FMA2(acc[0][2], ua.x, w2[2]); FMA2(acc[0][3], ua.x, w2[3]);
      FMA2(acc[1][0], ua.y, w2[0]); FMA2(acc[1][1], ua.y, w2[1]);
      FMA2(acc[1][2], ua.y, w2[2]); FMA2(acc[1][3], ua.y, w2[3]);
      FMA2(acc[2][0], ub.x, w2[0]); FMA2(acc[2][1], ub.x, w2[1]);
      FMA2(acc[2][2], ub.x, w2[2]); FMA2(acc[2][3], ub.x, w2[3]);
      FMA2(acc[3][0], ub.y, w2[0]); FMA2(acc[3][1], ub.y, w2[1]);
      FMA2(acc[3][2], ub.y, w2[2]); FMA2(acc[3][3], ub.y, w2[3]);
    }

    float cl[4], chv[4];
    if (MODE) {
      // agreement logits; reduce over eg via shfl (lane bits 3,4)
      u64 ag[4] = {0ull, 0ull, 0ull, 0ull};
#pragma unroll
      for (int k = 0; k < 4; k++)
#pragma unroll
        for (int j = 0; j < 4; j++) {
          u64 vp; PACK2(vp, vr[2 * k][j], vr[2 * k + 1][j]);
          FMA2(ag[k], acc[k][j], vp);
        }
      float al[4], ah[4];
#pragma unroll
      for (int k = 0; k < 4; k++) {
        UNPK2(al[k], ah[k], ag[k]);
        al[k] += __shfl_xor_sync(0xffffffffu, al[k], 8);
        al[k] += __shfl_xor_sync(0xffffffffu, al[k], 16);
        ah[k] += __shfl_xor_sync(0xffffffffu, ah[k], 8);
        ah[k] += __shfl_xor_sync(0xffffffffu, ah[k], 16);
      }
      if (eg == 0) {
        float* ar = ab + nl * kAPad + o;
#pragma unroll
        for (int k = 0; k < 4; k++) {
          ar[(2 * k) * kO]     = al[k];
          ar[(2 * k + 1) * kO] = ah[k];
        }
      }
      __syncthreads();
      if (tid < 64) {  // softmax over o for each (nl, b-of-chunk)
        float* row = ab + (tid & 7) * kAPad + (tid >> 3) * kO;
        float m = row[0];
#pragma unroll
        for (int i = 1; i < kO; i++) m = fmaxf(m, row[i]);
        float e[kO]; float ss = 0.f;
#pragma unroll
        for (int i = 0; i < kO; i++) { e[i] = __expf(row[i] - m); ss += e[i]; }
        float inv = 1.f / ss;
#pragma unroll
        for (int i = 0; i < kO; i++) row[i] = e[i] * inv;
      }
      __syncthreads();
      const float* ar = ab + nl * kAPad + o;
#pragma unroll
      for (int k = 0; k < 4; k++) {
        cl[k]  = ar[(2 * k) * kO];
        chv[k] = ar[(2 * k + 1) * kO];
      }
    }

    // ---- weight by c (in place) ----
    u64 v16[16];
#pragma unroll
    for (int k = 0; k < 4; k++) {
      u64 cp;
      if (MODE) { PACK2(cp, cl[k], chv[k]); }
      else      { PACK2(cp, 0.1f, 0.1f); }
#pragma unroll
      for (int j = 0; j < 4; j++) MUL2(v16[k * 4 + j], acc[k][j], cp);
    }

    // ---- reduce-scatter over nl (lane bits 0-2): 14 u64 shfl ----
    u64 v8[8];
    {
      const bool sel = (nl >> 2) & 1;
#pragma unroll
      for (int i = 0; i < 8; i++) {
        u64 send = sel ? v16[i] : v16[8 + i];
        u64 recv = __shfl_xor_sync(0xffffffffu, send, 4);
        u64 keep = sel ? v16[8 + i] : v16[i];
        ADD2(v8[i], keep, recv);
      }
    }
    u64 v4[4];
    {
      const bool sel = (nl >> 1) & 1;
#pragma unroll
      for (int i = 0; i < 4; i++) {
        u64 send = sel ? v8[i] : v8[4 + i];
        u64 recv = __shfl_xor_sync(0xffffffffu, send, 2);
        u64 keep = sel ? v8[4 + i] : v8[i];
        ADD2(v4[i], keep, recv);
      }
    }
    u64 v2[2];
    {
      const bool sel = nl & 1;
#pragma unroll
      for (int i = 0; i < 2; i++) {
        u64 send = sel ? v4[i] : v4[2 + i];
        u64 recv = __shfl_xor_sync(0xffffffffu, send, 1);
        u64 keep = sel ? v4[2 + i] : v4[i];
        ADD2(v2[i], keep, recv);
      }
    }

    // lane holds m = mm, mm+1: batch-pair kk, e-offsets j0, j0+1
    {
      float l0, h0, l1, h1;
      UNPK2(l0, h0, v2[0]); UNPK2(l1, h1, v2[1]);
      float* dp = &g_part[((size_t)blockIdx.x * kB + bc + 2 * kk) * kOE
                          + o * kE + eg * 4 + j0];
      *(float2*)dp         = make_float2(l0, l1);
      *(float2*)(dp + kOE) = make_float2(h0, h1);
    }
  }
}

// Reduce 144 partials + squash. 10240 threads: (b,o) x e-quarter; n2 via shfl.
__global__ void squash_kernel(float* __restrict__ out, int mode) {
  int gt = blockIdx.x * blockDim.x + threadIdx.x;
  if (gt >= kB * kO * 4) return;
  int eq = gt & 3, row = gt >> 2;      // row = b*10 + o
  const float* pp = g_part + (size_t)row * kE + eq * 4;
  float4 a = {0.f, 0.f, 0.f, 0.f};
#pragma unroll 4
  for (int p = 0; p < kGrid; p++) {
    float4 t = *(const float4*)(pp + (size_t)p * kB * kOE);
    a.x += t.x; a.y += t.y; a.z += t.z; a.w += t.w;
  }
  float n2 = a.x * a.x + a.y * a.y + a.z * a.z + a.w * a.w;
  n2 += __shfl_xor_sync(0xffffffffu, n2, 1);
  n2 += __shfl_xor_sync(0xffffffffu, n2, 2);
  float f = sqrtf(n2) / (1.f + n2);
  float4 v = make_float4(a.x * f, a.y * f, a.z * f, a.w * f);
  if (mode == 2) {
    *(float4*)(out + (size_t)row * kE + eq * 4) = v;
  } else if (mode == 1) {
    float4 old = *(const float4*)(g_vsum + (size_t)row * kE + eq * 4);
    v.x += old.x; v.y += old.y; v.z += old.z; v.w += old.w;
    *(float4*)(g_vsum + (size_t)row * kE + eq * 4) = v;
  } else {
    *(float4*)(g_vsum + (size_t)row * kE + eq * 4) = v;
  }
}

extern "C" void kernel_launch(void* const* d_in, const int* in_sizes, int n_in,
                              void* d_out, int out_size) {
  const float* u    = (const float*)d_in[0];
  const float* W    = (const float*)d_in[1];
  const float* bias = (const float*)d_in[2];
  float* out = (float*)d_out;

  cudaFuncSetAttribute((const void*)pass_kernel<0>,
                       cudaFuncAttributeMaxDynamicSharedMemorySize, kSmemBytes);
  cudaFuncSetAttribute((const void*)pass_kernel<1>,
                       cudaFuncAttributeMaxDynamicSharedMemorySize, kSmemBytes);

  noop_kernel<<<1, 32>>>();  // keeps ncu -s 5 -c 1 on the 2nd pass_kernel<1>

  pass_kernel<0><<<kGrid, kTH, kSmemBytes>>>(u, W, bias);
  squash_kernel<<<40, 256>>>(nullptr, 0);

  pass_kernel<1><<<kGrid, kTH, kSmemBytes>>>(u, W, bias);
  squash_kernel<<<40, 256>>>(nullptr, 1);

  pass_kernel<1><<<kGrid, kTH, kSmemBytes>>>(u, W, bias);
  squash_kernel<<<40, 256>>>(out, 2);
}